// round 3
// baseline (speedup 1.0000x reference)
#include <cuda_runtime.h>
#include <math.h>

// Problem constants
#define B      4
#define C      128
#define NSP    32768          // 32*32*32 spatial positions
#define HID    256            // heads * dim_head
#define M3     768            // 3 * HID (qkv rows)
#define HEADS  8
#define DH     32
#define QSCALE 0.17677669529663687f   // 32^-0.5
#define NSPLIT 32

// -------- device scratch (static allocation; no cudaMalloc allowed) --------
__device__ float g_qkv [(size_t)B * M3 * NSP];          // 384 MB: q|k|v rows
__device__ float g_kmax[B * HID];                       // per (b, h*32+d) row max of k
__device__ float g_ksum[B * HID];                       // per row sum exp
__device__ float g_qmax[(size_t)B * HEADS * NSP];       // per (b,h,n) q-col max
__device__ float g_qsum[(size_t)B * HEADS * NSP];       // per (b,h,n) q-col sumexp
__device__ float g_ctxp[(size_t)NSPLIT * B * HEADS * DH * DH]; // context partials
__device__ float g_M   [(size_t)B * C * HID];           // folded w_out * ctx^T

// ============================================================================
// K1: qkv = w_qkv[768,128] @ x[b][128,N]   (128x128x16 fp32 SGEMM,
//     double-buffered smem with register prefetch)
// grid (N/128, 768/128, B), 256 threads, 8x8 per thread
// ============================================================================
__global__ __launch_bounds__(256) void k_qkv(const float* __restrict__ x,
                                             const float* __restrict__ wqkv) {
    const int bz    = blockIdx.z;
    const int mBase = blockIdx.y * 128;
    const int nBase = blockIdx.x * 128;
    const float* Bp = x + (size_t)bz * C * NSP;
    float*       Cp = g_qkv + (size_t)bz * M3 * NSP;

    __shared__ float As[2][16][128];  // k-major A
    __shared__ float Bs[2][16][128];

    const int tid = threadIdx.x;
    const int tm  = (tid >> 4) << 3;
    const int tn  = (tid & 15) << 3;

    // per-thread load coordinates
    const int aRow0 = (tid * 2) >> 2,       aCol0 = ((tid * 2) & 3) << 2;
    const int aRow1 = (tid * 2 + 1) >> 2,   aCol1 = ((tid * 2 + 1) & 3) << 2;
    const int bRow0 = (tid * 2) >> 5,       bCol0 = ((tid * 2) & 31) << 2;
    const int bRow1 = (tid * 2 + 1) >> 5,   bCol1 = ((tid * 2 + 1) & 31) << 2;

    float acc[8][8] = {};

    // --- prologue: load k0 = 0 into buffer 0 ---
    float4 a0 = *(const float4*)&wqkv[(size_t)(mBase + aRow0) * C + aCol0];
    float4 a1 = *(const float4*)&wqkv[(size_t)(mBase + aRow1) * C + aCol1];
    float4 b0 = *(const float4*)&Bp[(size_t)bRow0 * NSP + nBase + bCol0];
    float4 b1 = *(const float4*)&Bp[(size_t)bRow1 * NSP + nBase + bCol1];
    As[0][aCol0 + 0][aRow0] = a0.x; As[0][aCol0 + 1][aRow0] = a0.y;
    As[0][aCol0 + 2][aRow0] = a0.z; As[0][aCol0 + 3][aRow0] = a0.w;
    As[0][aCol1 + 0][aRow1] = a1.x; As[0][aCol1 + 1][aRow1] = a1.y;
    As[0][aCol1 + 2][aRow1] = a1.z; As[0][aCol1 + 3][aRow1] = a1.w;
    *(float4*)&Bs[0][bRow0][bCol0] = b0;
    *(float4*)&Bs[0][bRow1][bCol1] = b1;
    __syncthreads();

    int buf = 0;
    for (int k0 = 0; k0 < C; k0 += 16) {
        const int kn = k0 + 16;
        const bool more = (kn < C);
        if (more) {   // prefetch next tile into registers
            a0 = *(const float4*)&wqkv[(size_t)(mBase + aRow0) * C + kn + aCol0];
            a1 = *(const float4*)&wqkv[(size_t)(mBase + aRow1) * C + kn + aCol1];
            b0 = *(const float4*)&Bp[(size_t)(kn + bRow0) * NSP + nBase + bCol0];
            b1 = *(const float4*)&Bp[(size_t)(kn + bRow1) * NSP + nBase + bCol1];
        }
#pragma unroll
        for (int k = 0; k < 16; k++) {
            float ar[8], br[8];
            *(float4*)&ar[0] = *(const float4*)&As[buf][k][tm];
            *(float4*)&ar[4] = *(const float4*)&As[buf][k][tm + 4];
            *(float4*)&br[0] = *(const float4*)&Bs[buf][k][tn];
            *(float4*)&br[4] = *(const float4*)&Bs[buf][k][tn + 4];
#pragma unroll
            for (int i = 0; i < 8; i++)
#pragma unroll
                for (int j = 0; j < 8; j++)
                    acc[i][j] = fmaf(ar[i], br[j], acc[i][j]);
        }
        if (more) {
            const int nb = buf ^ 1;
            As[nb][aCol0 + 0][aRow0] = a0.x; As[nb][aCol0 + 1][aRow0] = a0.y;
            As[nb][aCol0 + 2][aRow0] = a0.z; As[nb][aCol0 + 3][aRow0] = a0.w;
            As[nb][aCol1 + 0][aRow1] = a1.x; As[nb][aCol1 + 1][aRow1] = a1.y;
            As[nb][aCol1 + 2][aRow1] = a1.z; As[nb][aCol1 + 3][aRow1] = a1.w;
            *(float4*)&Bs[nb][bRow0][bCol0] = b0;
            *(float4*)&Bs[nb][bRow1][bCol1] = b1;
            __syncthreads();
            buf = nb;
        }
    }
#pragma unroll
    for (int i = 0; i < 8; i++) {
        float* cp = &Cp[(size_t)(mBase + tm + i) * NSP + nBase + tn];
        *(float4*)(cp + 0) = make_float4(acc[i][0], acc[i][1], acc[i][2], acc[i][3]);
        *(float4*)(cp + 4) = make_float4(acc[i][4], acc[i][5], acc[i][6], acc[i][7]);
    }
}

// ============================================================================
// K2: per k-row (b, h*32+d) max and sum(exp) over N   — 1024 blocks x 256 thr
// ============================================================================
__global__ __launch_bounds__(256) void k_kstats() {
    const int blk = blockIdx.x;                  // b*256 + r
    const int b = blk >> 8, r = blk & 255;
    const float* kp = g_qkv + ((size_t)b * M3 + HID + r) * NSP;
    const int tid = threadIdx.x;
    __shared__ float red[256];

    float m = -INFINITY;
    for (int i = tid; i < NSP; i += 1024) {
        float4 v = *(const float4*)&kp[i * 4 - tid * 3];  // dummy-free path below
        (void)v; break;
    }
    // vectorized max
    m = -INFINITY;
    for (int i = tid * 4; i < NSP; i += 1024) {
        float4 v = *(const float4*)&kp[i];
        m = fmaxf(m, fmaxf(fmaxf(v.x, v.y), fmaxf(v.z, v.w)));
    }
    red[tid] = m; __syncthreads();
    for (int off = 128; off > 0; off >>= 1) {
        if (tid < off) red[tid] = fmaxf(red[tid], red[tid + off]);
        __syncthreads();
    }
    const float M = red[0]; __syncthreads();

    float s = 0.f;
    for (int i = tid * 4; i < NSP; i += 1024) {
        float4 v = *(const float4*)&kp[i];
        s += __expf(v.x - M) + __expf(v.y - M) + __expf(v.z - M) + __expf(v.w - M);
    }
    red[tid] = s; __syncthreads();
    for (int off = 128; off > 0; off >>= 1) {
        if (tid < off) red[tid] += red[tid + off];
        __syncthreads();
    }
    if (tid == 0) { g_kmax[blk] = M; g_ksum[blk] = red[0]; }
}

// ============================================================================
// K3: per q-column (b,h,n): max & sumexp over the 32 feature rows
// grid (N/128, HEADS, B), 128 threads, column-per-thread (coalesced row reads)
// ============================================================================
__global__ __launch_bounds__(128) void k_qstats() {
    const int b = blockIdx.z, h = blockIdx.y;
    const int col = blockIdx.x * 128 + threadIdx.x;
    const float* qp = g_qkv + ((size_t)b * M3 + h * DH) * NSP + col;

    float vals[DH];
    float m = -INFINITY;
#pragma unroll
    for (int d = 0; d < DH; d++) { vals[d] = qp[(size_t)d * NSP]; m = fmaxf(m, vals[d]); }
    float s = 0.f;
#pragma unroll
    for (int d = 0; d < DH; d++) s += __expf(vals[d] - m);
    const size_t o = ((size_t)b * HEADS + h) * NSP + col;
    g_qmax[o] = m; g_qsum[o] = s;
}

// ============================================================================
// K4: context partials: ctx[b,h,d,e] += sum_n exp(k[d,n]-kmax[d]) * v[e,n]
// grid (NSPLIT, HEADS, B), 256 threads; each block handles 1024 n
// thread computes 2x2 of the 32x32 output
// ============================================================================
__global__ __launch_bounds__(256) void k_ctx() {
    const int sp = blockIdx.x, h = blockIdx.y, b = blockIdx.z;
    const float* kp = g_qkv + ((size_t)b * M3 + HID     + h * DH) * NSP;
    const float* vp = g_qkv + ((size_t)b * M3 + 2 * HID + h * DH) * NSP;

    __shared__ float ks[32][132];
    __shared__ float vs[32][132];
    __shared__ float kmax_s[32];

    const int tid = threadIdx.x;
    if (tid < 32) kmax_s[tid] = g_kmax[b * HID + h * DH + tid];
    __syncthreads();

    const int d0 = tid >> 4;   // 0..15
    const int e0 = tid & 15;   // 0..15
    float a00 = 0, a01 = 0, a10 = 0, a11 = 0;
    const int nb = sp * 1024;

    for (int t = 0; t < 8; t++) {
        const int n0 = nb + t * 128;
#pragma unroll
        for (int i = 0; i < 4; i++) {
            int v4 = tid + i * 256;
            int row = v4 >> 5, col = (v4 & 31) << 2;
            float4 kv = *(const float4*)&kp[(size_t)row * NSP + n0 + col];
            float  km = kmax_s[row];
            ks[row][col + 0] = __expf(kv.x - km);
            ks[row][col + 1] = __expf(kv.y - km);
            ks[row][col + 2] = __expf(kv.z - km);
            ks[row][col + 3] = __expf(kv.w - km);
            *(float4*)&vs[row][col] = *(const float4*)&vp[(size_t)row * NSP + n0 + col];
        }
        __syncthreads();
#pragma unroll
        for (int j = 0; j < 128; j += 4) {
            float4 ka = *(const float4*)&ks[d0][j];
            float4 kb = *(const float4*)&ks[d0 + 16][j];
            float4 va = *(const float4*)&vs[e0][j];
            float4 vb = *(const float4*)&vs[e0 + 16][j];
            a00 = fmaf(ka.x, va.x, fmaf(ka.y, va.y, fmaf(ka.z, va.z, fmaf(ka.w, va.w, a00))));
            a01 = fmaf(ka.x, vb.x, fmaf(ka.y, vb.y, fmaf(ka.z, vb.z, fmaf(ka.w, vb.w, a01))));
            a10 = fmaf(kb.x, va.x, fmaf(kb.y, va.y, fmaf(kb.z, va.z, fmaf(kb.w, va.w, a10))));
            a11 = fmaf(kb.x, vb.x, fmaf(kb.y, vb.y, fmaf(kb.z, vb.z, fmaf(kb.w, vb.w, a11))));
        }
        __syncthreads();
    }
    float* cp = &g_ctxp[(((size_t)sp * B + b) * HEADS + h) * (DH * DH)];
    cp[d0 * 32 + e0]             = a00;
    cp[d0 * 32 + e0 + 16]        = a01;
    cp[(d0 + 16) * 32 + e0]      = a10;
    cp[(d0 + 16) * 32 + e0 + 16] = a11;
}

// ============================================================================
// K5: reduce ctx partials, normalize by ksum, fold with w_out:
//     g_M[b][o][h*32+d] = sum_e w_out[o][h*32+e] * ctx[b,h,d,e]
// grid B, 256 threads
// ============================================================================
__global__ __launch_bounds__(256) void k_fold(const float* __restrict__ wout) {
    const int b = blockIdx.x;
    __shared__ float ctx[HEADS * DH * DH];   // [h][d][e], 32 KB
    const int tid = threadIdx.x;

    for (int idx = tid; idx < HEADS * DH * DH; idx += 256) {
        float s = 0.f;
        for (int sp = 0; sp < NSPLIT; sp++)
            s += g_ctxp[(((size_t)sp * B + b) * HEADS) * (DH * DH) + idx];
        const int h = idx >> 10, de = idx & 1023, d = de >> 5;
        ctx[idx] = s / g_ksum[b * HID + h * DH + d];
    }
    __syncthreads();

    for (int idx = tid; idx < C * HID; idx += 256) {
        const int o = idx >> 8, cc = idx & 255;
        const int h = cc >> 5, d = cc & 31;
        const float* wrow = &wout[o * HID + h * DH];
        const float* crow = &ctx[h * (DH * DH) + d * 32];
        float s = 0.f;
#pragma unroll
        for (int e = 0; e < DH; e++) s = fmaf(wrow[e], crow[e], s);
        g_M[(size_t)b * C * HID + idx] = s;
    }
}

// ============================================================================
// K6: out[b][o][n] = sum_c g_M[b][o][c] * q_sm[c][n] + b_out[o]
// q_sm generated on the fly: SCALE * exp(q - qmax)/qsum per head column
// grid (N/128, B), 256 threads, 8x8 per thread, K=256 in 16 steps,
// double-buffered smem with register prefetch
// ============================================================================
__global__ __launch_bounds__(256) void k_out(float* __restrict__ out,
                                             const float* __restrict__ bout) {
    const int b = blockIdx.y;
    const int nBase = blockIdx.x * 128;
    const float* qp = g_qkv + (size_t)b * M3 * NSP;
    const float* Mp = g_M + (size_t)b * C * HID;

    __shared__ float As[2][16][128];
    __shared__ float Bs[2][16][132];
    __shared__ float qmax_s [HEADS][128];
    __shared__ float qsinv_s[HEADS][128];
    __shared__ float bo[128];

    const int tid = threadIdx.x;
    for (int i = tid; i < HEADS * 128; i += 256) {
        const int h = i >> 7, j = i & 127;
        const size_t o = ((size_t)b * HEADS + h) * NSP + nBase + j;
        qmax_s [h][j] = g_qmax[o];
        qsinv_s[h][j] = QSCALE / g_qsum[o];
    }
    if (tid < 128) bo[tid] = bout[tid];

    const int tm = (tid >> 4) << 3;
    const int tn = (tid & 15) << 3;

    const int aRow0 = (tid * 2) >> 2,     aCol0 = ((tid * 2) & 3) << 2;
    const int aRow1 = (tid * 2 + 1) >> 2, aCol1 = ((tid * 2 + 1) & 3) << 2;
    const int bRow0 = (tid * 2) >> 5,     bCol0 = ((tid * 2) & 31) << 2;
    const int bRow1 = (tid * 2 + 1) >> 5, bCol1 = ((tid * 2 + 1) & 31) << 2;

    float acc[8][8] = {};

    // helper lambda-ish: compute softmaxed q values for a row of the B tile
    // (done inline at each store site)
    float4 a0 = *(const float4*)&Mp[(size_t)aRow0 * HID + aCol0];
    float4 a1 = *(const float4*)&Mp[(size_t)aRow1 * HID + aCol1];
    float4 b0 = *(const float4*)&qp[(size_t)bRow0 * NSP + nBase + bCol0];
    float4 b1 = *(const float4*)&qp[(size_t)bRow1 * NSP + nBase + bCol1];
    __syncthreads();   // qmax_s/qsinv_s ready

    {
        As[0][aCol0 + 0][aRow0] = a0.x; As[0][aCol0 + 1][aRow0] = a0.y;
        As[0][aCol0 + 2][aRow0] = a0.z; As[0][aCol0 + 3][aRow0] = a0.w;
        As[0][aCol1 + 0][aRow1] = a1.x; As[0][aCol1 + 1][aRow1] = a1.y;
        As[0][aCol1 + 2][aRow1] = a1.z; As[0][aCol1 + 3][aRow1] = a1.w;
        const int h0 = bRow0 >> 5;   // k0=0: cidx = bRow
        Bs[0][bRow0][bCol0 + 0] = __expf(b0.x - qmax_s[h0][bCol0 + 0]) * qsinv_s[h0][bCol0 + 0];
        Bs[0][bRow0][bCol0 + 1] = __expf(b0.y - qmax_s[h0][bCol0 + 1]) * qsinv_s[h0][bCol0 + 1];
        Bs[0][bRow0][bCol0 + 2] = __expf(b0.z - qmax_s[h0][bCol0 + 2]) * qsinv_s[h0][bCol0 + 2];
        Bs[0][bRow0][bCol0 + 3] = __expf(b0.w - qmax_s[h0][bCol0 + 3]) * qsinv_s[h0][bCol0 + 3];
        const int h1 = bRow1 >> 5;
        Bs[0][bRow1][bCol1 + 0] = __expf(b1.x - qmax_s[h1][bCol1 + 0]) * qsinv_s[h1][bCol1 + 0];
        Bs[0][bRow1][bCol1 + 1] = __expf(b1.y - qmax_s[h1][bCol1 + 1]) * qsinv_s[h1][bCol1 + 1];
        Bs[0][bRow1][bCol1 + 2] = __expf(b1.z - qmax_s[h1][bCol1 + 2]) * qsinv_s[h1][bCol1 + 2];
        Bs[0][bRow1][bCol1 + 3] = __expf(b1.w - qmax_s[h1][bCol1 + 3]) * qsinv_s[h1][bCol1 + 3];
    }
    __syncthreads();

    int buf = 0;
    for (int k0 = 0; k0 < HID; k0 += 16) {
        const int kn = k0 + 16;
        const bool more = (kn < HID);
        if (more) {
            a0 = *(const float4*)&Mp[(size_t)aRow0 * HID + kn + aCol0];
            a1 = *(const float4*)&Mp[(size_t)aRow1 * HID + kn + aCol1];
            b0 = *(const float4*)&qp[(size_t)(kn + bRow0) * NSP + nBase + bCol0];
            b1 = *(const float4*)&qp[(size_t)(kn + bRow1) * NSP + nBase + bCol1];
        }
#pragma unroll
        for (int k = 0; k < 16; k++) {
            float ar[8], br[8];
            *(float4*)&ar[0] = *(const float4*)&As[buf][k][tm];
            *(float4*)&ar[4] = *(const float4*)&As[buf][k][tm + 4];
            *(float4*)&br[0] = *(const float4*)&Bs[buf][k][tn];
            *(float4*)&br[4] = *(const float4*)&Bs[buf][k][tn + 4];
#pragma unroll
            for (int i = 0; i < 8; i++)
#pragma unroll
                for (int j = 0; j < 8; j++)
                    acc[i][j] = fmaf(ar[i], br[j], acc[i][j]);
        }
        if (more) {
            const int nb = buf ^ 1;
            As[nb][aCol0 + 0][aRow0] = a0.x; As[nb][aCol0 + 1][aRow0] = a0.y;
            As[nb][aCol0 + 2][aRow0] = a0.z; As[nb][aCol0 + 3][aRow0] = a0.w;
            As[nb][aCol1 + 0][aRow1] = a1.x; As[nb][aCol1 + 1][aRow1] = a1.y;
            As[nb][aCol1 + 2][aRow1] = a1.z; As[nb][aCol1 + 3][aRow1] = a1.w;
            const int h0 = (kn + bRow0) >> 5;
            Bs[nb][bRow0][bCol0 + 0] = __expf(b0.x - qmax_s[h0][bCol0 + 0]) * qsinv_s[h0][bCol0 + 0];
            Bs[nb][bRow0][bCol0 + 1] = __expf(b0.y - qmax_s[h0][bCol0 + 1]) * qsinv_s[h0][bCol0 + 1];
            Bs[nb][bRow0][bCol0 + 2] = __expf(b0.z - qmax_s[h0][bCol0 + 2]) * qsinv_s[h0][bCol0 + 2];
            Bs[nb][bRow0][bCol0 + 3] = __expf(b0.w - qmax_s[h0][bCol0 + 3]) * qsinv_s[h0][bCol0 + 3];
            const int h1 = (kn + bRow1) >> 5;
            Bs[nb][bRow1][bCol1 + 0] = __expf(b1.x - qmax_s[h1][bCol1 + 0]) * qsinv_s[h1][bCol1 + 0];
            Bs[nb][bRow1][bCol1 + 1] = __expf(b1.y - qmax_s[h1][bCol1 + 1]) * qsinv_s[h1][bCol1 + 1];
            Bs[nb][bRow1][bCol1 + 2] = __expf(b1.z - qmax_s[h1][bCol1 + 2]) * qsinv_s[h1][bCol1 + 2];
            Bs[nb][bRow1][bCol1 + 3] = __expf(b1.w - qmax_s[h1][bCol1 + 3]) * qsinv_s[h1][bCol1 + 3];
            __syncthreads();
            buf = nb;
        }
    }
#pragma unroll
    for (int i = 0; i < 8; i++) {
        const float bb = bo[tm + i];
        float* op = &out[((size_t)b * C + tm + i) * NSP + nBase + tn];
        *(float4*)(op + 0) = make_float4(acc[i][0] + bb, acc[i][1] + bb,
                                         acc[i][2] + bb, acc[i][3] + bb);
        *(float4*)(op + 4) = make_float4(acc[i][4] + bb, acc[i][5] + bb,
                                         acc[i][6] + bb, acc[i][7] + bb);
    }
}

// ============================================================================
extern "C" void kernel_launch(void* const* d_in, const int* in_sizes, int n_in,
                              void* d_out, int out_size) {
    const float* x    = (const float*)d_in[0];
    const float* wqkv = (const float*)d_in[1];
    const float* wout = (const float*)d_in[2];
    const float* bout = (const float*)d_in[3];
    float* out = (float*)d_out;

    k_qkv   <<<dim3(NSP / 128, M3 / 128, B), 256>>>(x, wqkv);
    k_kstats<<<B * HID, 256>>>();
    k_qstats<<<dim3(NSP / 128, HEADS, B), 128>>>();
    k_ctx   <<<dim3(NSPLIT, HEADS, B), 256>>>();
    k_fold  <<<B, 256>>>(wout);
    k_out   <<<dim3(NSP / 128, B), 256>>>(out, bout);
}

// round 6
// speedup vs baseline: 1.3222x; 1.3222x over previous
#include <cuda_runtime.h>
#include <cuda_bf16.h>
#include <math.h>
#include <stdint.h>

// Problem constants
#define B      4
#define C      128
#define NSP    32768          // 32*32*32 spatial positions
#define HID    256            // heads * dim_head
#define M3     768            // 3 * HID (qkv rows)
#define HEADS  8
#define DH     32
#define QSCALE 0.17677669529663687f   // 32^-0.5
#define NSPLIT 32

// -------- device scratch (static allocation; no cudaMalloc allowed) --------
__device__ float g_qkv [(size_t)B * M3 * NSP];          // 384 MB: q|k|v rows
__device__ float g_kmax[B * HID];
__device__ float g_ksum[B * HID];
__device__ float g_qmax[(size_t)B * HEADS * NSP];
__device__ float g_qsum[(size_t)B * HEADS * NSP];
__device__ float g_ctxp[(size_t)NSPLIT * B * HEADS * DH * DH];
__device__ float g_M   [(size_t)B * C * HID];
// bf16 split operands for the tensor-core qkv GEMM
__device__ __nv_bfloat16 g_xt_hi[(size_t)B * NSP * C];  // x transposed [b][n][c], hi
__device__ __nv_bfloat16 g_xt_lo[(size_t)B * NSP * C];  // lo part
__device__ __nv_bfloat16 g_w_hi [M3 * C];
__device__ __nv_bfloat16 g_w_lo [M3 * C];

// ============================================================================
// warp-MMA helpers (baseline PTX: works on compute_103 target)
// ============================================================================
__device__ __forceinline__ uint32_t smem_u32(const void* p) {
    uint32_t a;
    asm("{ .reg .u64 t; cvta.to.shared.u64 t, %1; cvt.u32.u64 %0, t; }"
        : "=r"(a) : "l"(p));
    return a;
}
__device__ __forceinline__ void ldsm4(uint32_t* r, uint32_t addr) {
    asm volatile("ldmatrix.sync.aligned.m8n8.x4.shared.b16 {%0,%1,%2,%3}, [%4];"
                 : "=r"(r[0]), "=r"(r[1]), "=r"(r[2]), "=r"(r[3]) : "r"(addr));
}
__device__ __forceinline__ void mma_bf16(float* d, const uint32_t* a,
                                         const uint32_t* b) {
    asm volatile(
        "mma.sync.aligned.m16n8k16.row.col.f32.bf16.bf16.f32 "
        "{%0,%1,%2,%3}, {%4,%5,%6,%7}, {%8,%9}, {%0,%1,%2,%3};"
        : "+f"(d[0]), "+f"(d[1]), "+f"(d[2]), "+f"(d[3])
        : "r"(a[0]), "r"(a[1]), "r"(a[2]), "r"(a[3]), "r"(b[0]), "r"(b[1]));
}

// smem layout for k_qkv_mma (bytes); row stride 136 bf16 = 272 B (pad => no
// ldmatrix bank conflicts: 8 consecutive rows land on distinct bank quads)
#define QK_STRIDE 136
#define QK_TILE_B (128 * QK_STRIDE * 2)     // 34816 per operand tile
#define QS_AHI 0
#define QS_ALO (QS_AHI + QK_TILE_B)
#define QS_BHI (QS_ALO + QK_TILE_B)
#define QS_BLO (QS_BHI + QK_TILE_B)
#define QS_TOTAL (QS_BLO + QK_TILE_B)       // 139264

// ============================================================================
// conversion kernels: fp32 -> (hi, lo) bf16 split
// ============================================================================
__global__ __launch_bounds__(256) void k_cvt_w(const float* __restrict__ w) {
    const int idx = blockIdx.x * 256 + threadIdx.x;
    if (idx < M3 * C) {
        float v = w[idx];
        __nv_bfloat16 h = __float2bfloat16(v);
        g_w_hi[idx] = h;
        g_w_lo[idx] = __float2bfloat16(v - __bfloat162float(h));
    }
}

// transpose x [b][c][n] fp32 -> x_t [b][n][c] bf16 hi/lo
__global__ __launch_bounds__(256) void k_cvt_x(const float* __restrict__ x) {
    __shared__ float t[32][33];
    const int bz = blockIdx.z;
    const int c0 = blockIdx.y * 32, n0 = blockIdx.x * 32;
    const int tx = threadIdx.x, ty = threadIdx.y;
    const float* xp = x + (size_t)bz * C * NSP;
#pragma unroll
    for (int j = 0; j < 4; j++)
        t[ty + 8 * j][tx] = xp[(size_t)(c0 + ty + 8 * j) * NSP + n0 + tx];
    __syncthreads();
    __nv_bfloat16* oh = g_xt_hi + (size_t)bz * NSP * C;
    __nv_bfloat16* ol = g_xt_lo + (size_t)bz * NSP * C;
#pragma unroll
    for (int j = 0; j < 4; j++) {
        const int n = n0 + ty + 8 * j, c = c0 + tx;
        float v = t[tx][ty + 8 * j];
        __nv_bfloat16 h = __float2bfloat16(v);
        oh[(size_t)n * C + c] = h;
        ol[(size_t)n * C + c] = __float2bfloat16(v - __bfloat162float(h));
    }
}

// ============================================================================
// K1 (tensor core via mma.sync): qkv = w_qkv @ x, bf16 hi/lo split (3 chains).
// grid (6 m-blocks, 256 n-blocks, B), 256 threads (8 warps, 2x4).
// CTA tile 128(m) x 128(n), K=128 fully resident. Warp: 64x32 via 4x4
// m16n8k16 tiles, fp32 accumulate. Epilogue staged through smem for
// coalesced float4 stores.
// ============================================================================
__global__ __launch_bounds__(256) void k_qkv_mma() {
    extern __shared__ char smem[];
    const int tid = threadIdx.x, wid = tid >> 5, lane = tid & 31;
    const int bz = blockIdx.z;
    const int mBase = blockIdx.x * 128, nBase = blockIdx.y * 128;

    // ---- cooperative tile loads: 128 rows x 128 bf16, stride 136 ----
    {
        const __nv_bfloat16* xh = g_xt_hi + (size_t)bz * NSP * C;
        const __nv_bfloat16* xl = g_xt_lo + (size_t)bz * NSP * C;
        __nv_bfloat16* sAh = (__nv_bfloat16*)(smem + QS_AHI);
        __nv_bfloat16* sAl = (__nv_bfloat16*)(smem + QS_ALO);
        __nv_bfloat16* sBh = (__nv_bfloat16*)(smem + QS_BHI);
        __nv_bfloat16* sBl = (__nv_bfloat16*)(smem + QS_BLO);
#pragma unroll
        for (int it = 0; it < 8; it++) {
            const int idx = it * 256 + tid;        // 2048 uint4 per tile
            const int row = idx >> 4, c8 = (idx & 15) << 3;
            const int so = row * QK_STRIDE + c8;
            const size_t ga = (size_t)(mBase + row) * C + c8;
            const size_t gb = (size_t)(nBase + row) * C + c8;
            *(uint4*)&sAh[so] = *(const uint4*)&g_w_hi[ga];
            *(uint4*)&sAl[so] = *(const uint4*)&g_w_lo[ga];
            *(uint4*)&sBh[so] = *(const uint4*)&xh[gb];
            *(uint4*)&sBl[so] = *(const uint4*)&xl[gb];
        }
    }
    __syncthreads();

    const uint32_t sb = smem_u32(smem);
    const int warpM = (wid >> 2) * 64;     // 0 or 64
    const int warpN = (wid & 3) * 32;      // 0..96

    // per-lane ldmatrix addresses (byte offsets within a tile)
    // A: mats (rows0-7,k0-7),(rows8-15,k0-7),(rows0-7,k+8),(rows8-15,k+8)
    const uint32_t aOff =
        (uint32_t)((warpM + (lane & 15)) * QK_STRIDE + ((lane >> 4) << 3)) * 2;
    // B: g = lane>>3: (n+0,k0),(n+0,k+8),(n+8,k0),(n+8,k+8)
    const int bg = lane >> 3;
    const uint32_t bOff =
        (uint32_t)((warpN + ((bg >> 1) << 3) + (lane & 7)) * QK_STRIDE +
                   ((bg & 1) << 3)) * 2;

    float acc[4][4][4] = {};

#pragma unroll
    for (int ks = 0; ks < 8; ks++) {
        const uint32_t kOff = (uint32_t)ks * 32;   // 16 bf16 = 32 B
        // B fragments: 2 x4 per operand (each covers 2 n-tiles x k16)
        uint32_t bh[4][2], bl[4][2];
#pragma unroll
        for (int p = 0; p < 2; p++) {
            const uint32_t po = (uint32_t)(p * 16 * QK_STRIDE * 2);
            uint32_t r[4];
            ldsm4(r, sb + QS_BHI + bOff + po + kOff);
            bh[p * 2][0] = r[0]; bh[p * 2][1] = r[1];
            bh[p * 2 + 1][0] = r[2]; bh[p * 2 + 1][1] = r[3];
            ldsm4(r, sb + QS_BLO + bOff + po + kOff);
            bl[p * 2][0] = r[0]; bl[p * 2][1] = r[1];
            bl[p * 2 + 1][0] = r[2]; bl[p * 2 + 1][1] = r[3];
        }
#pragma unroll
        for (int mi = 0; mi < 4; mi++) {
            const uint32_t mo = (uint32_t)(mi * 16 * QK_STRIDE * 2);
            uint32_t ah[4], al[4];
            ldsm4(ah, sb + QS_AHI + aOff + mo + kOff);
            ldsm4(al, sb + QS_ALO + aOff + mo + kOff);
#pragma unroll
            for (int ni = 0; ni < 4; ni++) {
                mma_bf16(acc[mi][ni], ah, bh[ni]);
                mma_bf16(acc[mi][ni], ah, bl[ni]);
                mma_bf16(acc[mi][ni], al, bh[ni]);
            }
        }
    }

    // ---- epilogue: stage to smem, then coalesced float4 stores ----
    __syncthreads();                       // operand tiles dead; reuse smem
    float* stage = (float*)smem;           // [128][132]
#pragma unroll
    for (int mi = 0; mi < 4; mi++) {
        const int r0 = warpM + mi * 16 + (lane >> 2);
#pragma unroll
        for (int ni = 0; ni < 4; ni++) {
            const int c0 = warpN + ni * 8 + (lane & 3) * 2;
            stage[r0 * 132 + c0]           = acc[mi][ni][0];
            stage[r0 * 132 + c0 + 1]       = acc[mi][ni][1];
            stage[(r0 + 8) * 132 + c0]     = acc[mi][ni][2];
            stage[(r0 + 8) * 132 + c0 + 1] = acc[mi][ni][3];
        }
    }
    __syncthreads();
    float* Cp = g_qkv + ((size_t)bz * M3 + mBase) * NSP + nBase;
#pragma unroll
    for (int it = 0; it < 16; it++) {
        const int idx = it * 256 + tid;
        const int row = idx >> 5, c4 = (idx & 31) << 2;
        *(float4*)&Cp[(size_t)row * NSP + c4] = *(float4*)&stage[row * 132 + c4];
    }
}

// ============================================================================
// K2: per k-row (b, h*32+d) max and sum(exp) over N
// ============================================================================
__global__ __launch_bounds__(256) void k_kstats() {
    const int blk = blockIdx.x;
    const int b = blk >> 8, r = blk & 255;
    const float* kp = g_qkv + ((size_t)b * M3 + HID + r) * NSP;
    const int tid = threadIdx.x;
    __shared__ float red[256];

    float m = -INFINITY;
    for (int i = tid * 4; i < NSP; i += 1024) {
        float4 v = *(const float4*)&kp[i];
        m = fmaxf(m, fmaxf(fmaxf(v.x, v.y), fmaxf(v.z, v.w)));
    }
    red[tid] = m; __syncthreads();
    for (int off = 128; off > 0; off >>= 1) {
        if (tid < off) red[tid] = fmaxf(red[tid], red[tid + off]);
        __syncthreads();
    }
    const float M = red[0]; __syncthreads();

    float s = 0.f;
    for (int i = tid * 4; i < NSP; i += 1024) {
        float4 v = *(const float4*)&kp[i];
        s += __expf(v.x - M) + __expf(v.y - M) + __expf(v.z - M) + __expf(v.w - M);
    }
    red[tid] = s; __syncthreads();
    for (int off = 128; off > 0; off >>= 1) {
        if (tid < off) red[tid] += red[tid + off];
        __syncthreads();
    }
    if (tid == 0) { g_kmax[blk] = M; g_ksum[blk] = red[0]; }
}

// ============================================================================
// K3: per q-column (b,h,n): max & sumexp over 32 feature rows
// ============================================================================
__global__ __launch_bounds__(128) void k_qstats() {
    const int b = blockIdx.z, h = blockIdx.y;
    const int col = blockIdx.x * 128 + threadIdx.x;
    const float* qp = g_qkv + ((size_t)b * M3 + h * DH) * NSP + col;

    float vals[DH];
    float m = -INFINITY;
#pragma unroll
    for (int d = 0; d < DH; d++) { vals[d] = qp[(size_t)d * NSP]; m = fmaxf(m, vals[d]); }
    float s = 0.f;
#pragma unroll
    for (int d = 0; d < DH; d++) s += __expf(vals[d] - m);
    const size_t o = ((size_t)b * HEADS + h) * NSP + col;
    g_qmax[o] = m; g_qsum[o] = s;
}

// ============================================================================
// K4: context partials: ctx[b,h,d,e] += sum_n exp(k[d,n]-kmax[d]) * v[e,n]
// ============================================================================
__global__ __launch_bounds__(256) void k_ctx() {
    const int sp = blockIdx.x, h = blockIdx.y, b = blockIdx.z;
    const float* kp = g_qkv + ((size_t)b * M3 + HID     + h * DH) * NSP;
    const float* vp = g_qkv + ((size_t)b * M3 + 2 * HID + h * DH) * NSP;

    __shared__ float ks[32][132];
    __shared__ float vs[32][132];
    __shared__ float kmax_s[32];

    const int tid = threadIdx.x;
    if (tid < 32) kmax_s[tid] = g_kmax[b * HID + h * DH + tid];
    __syncthreads();

    const int d0 = tid >> 4;
    const int e0 = tid & 15;
    float a00 = 0, a01 = 0, a10 = 0, a11 = 0;
    const int nb = sp * 1024;

    for (int t = 0; t < 8; t++) {
        const int n0 = nb + t * 128;
#pragma unroll
        for (int i = 0; i < 4; i++) {
            int v4 = tid + i * 256;
            int row = v4 >> 5, col = (v4 & 31) << 2;
            float4 kv = *(const float4*)&kp[(size_t)row * NSP + n0 + col];
            float  km = kmax_s[row];
            ks[row][col + 0] = __expf(kv.x - km);
            ks[row][col + 1] = __expf(kv.y - km);
            ks[row][col + 2] = __expf(kv.z - km);
            ks[row][col + 3] = __expf(kv.w - km);
            *(float4*)&vs[row][col] = *(const float4*)&vp[(size_t)row * NSP + n0 + col];
        }
        __syncthreads();
#pragma unroll
        for (int j = 0; j < 128; j += 4) {
            float4 ka = *(const float4*)&ks[d0][j];
            float4 kb = *(const float4*)&ks[d0 + 16][j];
            float4 va = *(const float4*)&vs[e0][j];
            float4 vb = *(const float4*)&vs[e0 + 16][j];
            a00 = fmaf(ka.x, va.x, fmaf(ka.y, va.y, fmaf(ka.z, va.z, fmaf(ka.w, va.w, a00))));
            a01 = fmaf(ka.x, vb.x, fmaf(ka.y, vb.y, fmaf(ka.z, vb.z, fmaf(ka.w, vb.w, a01))));
            a10 = fmaf(kb.x, va.x, fmaf(kb.y, va.y, fmaf(kb.z, va.z, fmaf(kb.w, va.w, a10))));
            a11 = fmaf(kb.x, vb.x, fmaf(kb.y, vb.y, fmaf(kb.z, vb.z, fmaf(kb.w, vb.w, a11))));
        }
        __syncthreads();
    }
    float* cp = &g_ctxp[(((size_t)sp * B + b) * HEADS + h) * (DH * DH)];
    cp[d0 * 32 + e0]             = a00;
    cp[d0 * 32 + e0 + 16]        = a01;
    cp[(d0 + 16) * 32 + e0]      = a10;
    cp[(d0 + 16) * 32 + e0 + 16] = a11;
}

// ============================================================================
// K5: reduce ctx partials, normalize by ksum, fold with w_out
// ============================================================================
__global__ __launch_bounds__(256) void k_fold(const float* __restrict__ wout) {
    const int b = blockIdx.x;
    __shared__ float ctx[HEADS * DH * DH];
    const int tid = threadIdx.x;

    for (int idx = tid; idx < HEADS * DH * DH; idx += 256) {
        float s = 0.f;
        for (int sp = 0; sp < NSPLIT; sp++)
            s += g_ctxp[(((size_t)sp * B + b) * HEADS) * (DH * DH) + idx];
        const int h = idx >> 10, de = idx & 1023, d = de >> 5;
        ctx[idx] = s / g_ksum[b * HID + h * DH + d];
    }
    __syncthreads();

    for (int idx = tid; idx < C * HID; idx += 256) {
        const int o = idx >> 8, cc = idx & 255;
        const int h = cc >> 5, d = cc & 31;
        const float* wrow = &wout[o * HID + h * DH];
        const float* crow = &ctx[h * (DH * DH) + d * 32];
        float s = 0.f;
#pragma unroll
        for (int e = 0; e < DH; e++) s = fmaf(wrow[e], crow[e], s);
        g_M[(size_t)b * C * HID + idx] = s;
    }
}

// ============================================================================
// K6: out[b][o][n] = sum_c g_M[b][o][c] * q_sm[c][n] + b_out[o]
// (fp32, double-buffered; q-softmax generated on the fly)
// ============================================================================
__global__ __launch_bounds__(256) void k_out(float* __restrict__ out,
                                             const float* __restrict__ bout) {
    const int b = blockIdx.y;
    const int nBase = blockIdx.x * 128;
    const float* qp = g_qkv + (size_t)b * M3 * NSP;
    const float* Mp = g_M + (size_t)b * C * HID;

    __shared__ float As[2][16][128];
    __shared__ float Bs[2][16][132];
    __shared__ float qmax_s [HEADS][128];
    __shared__ float qsinv_s[HEADS][128];
    __shared__ float bo[128];

    const int tid = threadIdx.x;
    for (int i = tid; i < HEADS * 128; i += 256) {
        const int h = i >> 7, j = i & 127;
        const size_t o = ((size_t)b * HEADS + h) * NSP + nBase + j;
        qmax_s [h][j] = g_qmax[o];
        qsinv_s[h][j] = QSCALE / g_qsum[o];
    }
    if (tid < 128) bo[tid] = bout[tid];

    const int tm = (tid >> 4) << 3;
    const int tn = (tid & 15) << 3;

    const int aRow0 = (tid * 2) >> 2,     aCol0 = ((tid * 2) & 3) << 2;
    const int aRow1 = (tid * 2 + 1) >> 2, aCol1 = ((tid * 2 + 1) & 3) << 2;
    const int bRow0 = (tid * 2) >> 5,     bCol0 = ((tid * 2) & 31) << 2;
    const int bRow1 = (tid * 2 + 1) >> 5, bCol1 = ((tid * 2 + 1) & 31) << 2;

    float acc[8][8] = {};

    float4 a0 = *(const float4*)&Mp[(size_t)aRow0 * HID + aCol0];
    float4 a1 = *(const float4*)&Mp[(size_t)aRow1 * HID + aCol1];
    float4 b0 = *(const float4*)&qp[(size_t)bRow0 * NSP + nBase + bCol0];
    float4 b1 = *(const float4*)&qp[(size_t)bRow1 * NSP + nBase + bCol1];
    __syncthreads();

    {
        As[0][aCol0 + 0][aRow0] = a0.x; As[0][aCol0 + 1][aRow0] = a0.y;
        As[0][aCol0 + 2][aRow0] = a0.z; As[0][aCol0 + 3][aRow0] = a0.w;
        As[0][aCol1 + 0][aRow1] = a1.x; As[0][aCol1 + 1][aRow1] = a1.y;
        As[0][aCol1 + 2][aRow1] = a1.z; As[0][aCol1 + 3][aRow1] = a1.w;
        const int h0 = bRow0 >> 5;
        Bs[0][bRow0][bCol0 + 0] = __expf(b0.x - qmax_s[h0][bCol0 + 0]) * qsinv_s[h0][bCol0 + 0];
        Bs[0][bRow0][bCol0 + 1] = __expf(b0.y - qmax_s[h0][bCol0 + 1]) * qsinv_s[h0][bCol0 + 1];
        Bs[0][bRow0][bCol0 + 2] = __expf(b0.z - qmax_s[h0][bCol0 + 2]) * qsinv_s[h0][bCol0 + 2];
        Bs[0][bRow0][bCol0 + 3] = __expf(b0.w - qmax_s[h0][bCol0 + 3]) * qsinv_s[h0][bCol0 + 3];
        const int h1 = bRow1 >> 5;
        Bs[0][bRow1][bCol1 + 0] = __expf(b1.x - qmax_s[h1][bCol1 + 0]) * qsinv_s[h1][bCol1 + 0];
        Bs[0][bRow1][bCol1 + 1] = __expf(b1.y - qmax_s[h1][bCol1 + 1]) * qsinv_s[h1][bCol1 + 1];
        Bs[0][bRow1][bCol1 + 2] = __expf(b1.z - qmax_s[h1][bCol1 + 2]) * qsinv_s[h1][bCol1 + 2];
        Bs[0][bRow1][bCol1 + 3] = __expf(b1.w - qmax_s[h1][bCol1 + 3]) * qsinv_s[h1][bCol1 + 3];
    }
    __syncthreads();

    int buf = 0;
    for (int k0 = 0; k0 < HID; k0 += 16) {
        const int kn = k0 + 16;
        const bool more = (kn < HID);
        if (more) {
            a0 = *(const float4*)&Mp[(size_t)aRow0 * HID + kn + aCol0];
            a1 = *(const float4*)&Mp[(size_t)aRow1 * HID + kn + aCol1];
            b0 = *(const float4*)&qp[(size_t)(kn + bRow0) * NSP + nBase + bCol0];
            b1 = *(const float4*)&qp[(size_t)(kn + bRow1) * NSP + nBase + bCol1];
        }
#pragma unroll
        for (int k = 0; k < 16; k++) {
            float ar[8], br[8];
            *(float4*)&ar[0] = *(const float4*)&As[buf][k][tm];
            *(float4*)&ar[4] = *(const float4*)&As[buf][k][tm + 4];
            *(float4*)&br[0] = *(const float4*)&Bs[buf][k][tn];
            *(float4*)&br[4] = *(const float4*)&Bs[buf][k][tn + 4];
#pragma unroll
            for (int i = 0; i < 8; i++)
#pragma unroll
                for (int j = 0; j < 8; j++)
                    acc[i][j] = fmaf(ar[i], br[j], acc[i][j]);
        }
        if (more) {
            const int nb = buf ^ 1;
            As[nb][aCol0 + 0][aRow0] = a0.x; As[nb][aCol0 + 1][aRow0] = a0.y;
            As[nb][aCol0 + 2][aRow0] = a0.z; As[nb][aCol0 + 3][aRow0] = a0.w;
            As[nb][aCol1 + 0][aRow1] = a1.x; As[nb][aCol1 + 1][aRow1] = a1.y;
            As[nb][aCol1 + 2][aRow1] = a1.z; As[nb][aCol1 + 3][aRow1] = a1.w;
            const int h0 = (kn + bRow0) >> 5;
            Bs[nb][bRow0][bCol0 + 0] = __expf(b0.x - qmax_s[h0][bCol0 + 0]) * qsinv_s[h0][bCol0 + 0];
            Bs[nb][bRow0][bCol0 + 1] = __expf(b0.y - qmax_s[h0][bCol0 + 1]) * qsinv_s[h0][bCol0 + 1];
            Bs[nb][bRow0][bCol0 + 2] = __expf(b0.z - qmax_s[h0][bCol0 + 2]) * qsinv_s[h0][bCol0 + 2];
            Bs[nb][bRow0][bCol0 + 3] = __expf(b0.w - qmax_s[h0][bCol0 + 3]) * qsinv_s[h0][bCol0 + 3];
            const int h1 = (kn + bRow1) >> 5;
            Bs[nb][bRow1][bCol1 + 0] = __expf(b1.x - qmax_s[h1][bCol1 + 0]) * qsinv_s[h1][bCol1 + 0];
            Bs[nb][bRow1][bCol1 + 1] = __expf(b1.y - qmax_s[h1][bCol1 + 1]) * qsinv_s[h1][bCol1 + 1];
            Bs[nb][bRow1][bCol1 + 2] = __expf(b1.z - qmax_s[h1][bCol1 + 2]) * qsinv_s[h1][bCol1 + 2];
            Bs[nb][bRow1][bCol1 + 3] = __expf(b1.w - qmax_s[h1][bCol1 + 3]) * qsinv_s[h1][bCol1 + 3];
            __syncthreads();
            buf = nb;
        }
    }
#pragma unroll
    for (int i = 0; i < 8; i++) {
        const float bb = bo[tm + i];
        float* op = &out[((size_t)b * C + tm + i) * NSP + nBase + tn];
        *(float4*)(op + 0) = make_float4(acc[i][0] + bb, acc[i][1] + bb,
                                         acc[i][2] + bb, acc[i][3] + bb);
        *(float4*)(op + 4) = make_float4(acc[i][4] + bb, acc[i][5] + bb,
                                         acc[i][6] + bb, acc[i][7] + bb);
    }
}

// ============================================================================
extern "C" void kernel_launch(void* const* d_in, const int* in_sizes, int n_in,
                              void* d_out, int out_size) {
    const float* x    = (const float*)d_in[0];
    const float* wqkv = (const float*)d_in[1];
    const float* wout = (const float*)d_in[2];
    const float* bout = (const float*)d_in[3];
    float* out = (float*)d_out;

    cudaFuncSetAttribute(k_qkv_mma, cudaFuncAttributeMaxDynamicSharedMemorySize,
                         QS_TOTAL);

    k_cvt_w  <<<(M3 * C + 255) / 256, 256>>>(wqkv);
    k_cvt_x  <<<dim3(NSP / 32, C / 32, B), dim3(32, 8)>>>(x);
    k_qkv_mma<<<dim3(M3 / 128, NSP / 128, B), 256, QS_TOTAL>>>();
    k_kstats <<<B * HID, 256>>>();
    k_qstats <<<dim3(NSP / 128, HEADS, B), 128>>>();
    k_ctx    <<<dim3(NSPLIT, HEADS, B), 256>>>();
    k_fold   <<<B, 256>>>(wout);
    k_out    <<<dim3(NSP / 128, B), 256>>>(out, bout);
}

// round 7
// speedup vs baseline: 1.5647x; 1.1835x over previous
#include <cuda_runtime.h>
#include <cuda_bf16.h>
#include <math.h>
#include <stdint.h>

// Problem constants
#define B      4
#define C      128
#define NSP    32768          // 32*32*32 spatial positions
#define HID    256            // heads * dim_head
#define M3     768            // 3 * HID (qkv rows)
#define HEADS  8
#define DH     32
#define QSCALE 0.17677669529663687f   // 32^-0.5
#define NSPLIT 32

// -------- device scratch (static allocation; no cudaMalloc allowed) --------
__device__ float g_qkv [(size_t)B * M3 * NSP];          // 384 MB: q|k|v rows
__device__ float g_ctxp[(size_t)NSPLIT * B * HEADS * DH * DH]; // context partials
__device__ float g_ksump[NSPLIT * B * HID];             // partial sum exp(k) per row
// bf16 split operands for tensor-core GEMMs
__device__ __nv_bfloat16 g_xt_hi[(size_t)B * NSP * C];  // x^T [b][n][c], hi
__device__ __nv_bfloat16 g_xt_lo[(size_t)B * NSP * C];  // lo
__device__ __nv_bfloat16 g_w_hi [M3 * C];
__device__ __nv_bfloat16 g_w_lo [M3 * C];
__device__ __nv_bfloat16 g_pt_hi[(size_t)B * NSP * HID]; // softmaxed q^T [b][n][c]
__device__ __nv_bfloat16 g_pt_lo[(size_t)B * NSP * HID];
__device__ __nv_bfloat16 g_M_hi [(size_t)B * C * HID];   // folded w_out*ctx^T
__device__ __nv_bfloat16 g_M_lo [(size_t)B * C * HID];

// ============================================================================
// warp-MMA helpers (baseline PTX: works on compute_103 target)
// ============================================================================
__device__ __forceinline__ uint32_t smem_u32(const void* p) {
    uint32_t a;
    asm("{ .reg .u64 t; cvta.to.shared.u64 t, %1; cvt.u32.u64 %0, t; }"
        : "=r"(a) : "l"(p));
    return a;
}
__device__ __forceinline__ void ldsm4(uint32_t* r, uint32_t addr) {
    asm volatile("ldmatrix.sync.aligned.m8n8.x4.shared.b16 {%0,%1,%2,%3}, [%4];"
                 : "=r"(r[0]), "=r"(r[1]), "=r"(r[2]), "=r"(r[3]) : "r"(addr));
}
__device__ __forceinline__ void mma_bf16(float* d, const uint32_t* a,
                                         const uint32_t* b) {
    asm volatile(
        "mma.sync.aligned.m16n8k16.row.col.f32.bf16.bf16.f32 "
        "{%0,%1,%2,%3}, {%4,%5,%6,%7}, {%8,%9}, {%0,%1,%2,%3};"
        : "+f"(d[0]), "+f"(d[1]), "+f"(d[2]), "+f"(d[3])
        : "r"(a[0]), "r"(a[1]), "r"(a[2]), "r"(a[3]), "r"(b[0]), "r"(b[1]));
}

// smem layout for the mma GEMMs; row stride 136 bf16 = 272 B (pad)
#define QK_STRIDE 136
#define QK_TILE_B (128 * QK_STRIDE * 2)     // 34816 per operand tile
#define QS_AHI 0
#define QS_ALO (QS_AHI + QK_TILE_B)
#define QS_BHI (QS_ALO + QK_TILE_B)
#define QS_BLO (QS_BHI + QK_TILE_B)
#define QS_TOTAL (QS_BLO + QK_TILE_B)       // 139264

// ============================================================================
// conversion kernels: fp32 -> (hi, lo) bf16 split
// ============================================================================
__global__ __launch_bounds__(256) void k_cvt_w(const float* __restrict__ w) {
    const int idx = blockIdx.x * 256 + threadIdx.x;
    if (idx < M3 * C) {
        float v = w[idx];
        __nv_bfloat16 h = __float2bfloat16(v);
        g_w_hi[idx] = h;
        g_w_lo[idx] = __float2bfloat16(v - __bfloat162float(h));
    }
}

// transpose x [b][c][n] fp32 -> x_t [b][n][c] bf16 hi/lo
__global__ __launch_bounds__(256) void k_cvt_x(const float* __restrict__ x) {
    __shared__ float t[32][33];
    const int bz = blockIdx.z;
    const int c0 = blockIdx.y * 32, n0 = blockIdx.x * 32;
    const int tx = threadIdx.x, ty = threadIdx.y;
    const float* xp = x + (size_t)bz * C * NSP;
#pragma unroll
    for (int j = 0; j < 4; j++)
        t[ty + 8 * j][tx] = xp[(size_t)(c0 + ty + 8 * j) * NSP + n0 + tx];
    __syncthreads();
    __nv_bfloat16* oh = g_xt_hi + (size_t)bz * NSP * C;
    __nv_bfloat16* ol = g_xt_lo + (size_t)bz * NSP * C;
#pragma unroll
    for (int j = 0; j < 4; j++) {
        const int n = n0 + ty + 8 * j, c = c0 + tx;
        float v = t[tx][ty + 8 * j];
        __nv_bfloat16 h = __float2bfloat16(v);
        oh[(size_t)n * C + c] = h;
        ol[(size_t)n * C + c] = __float2bfloat16(v - __bfloat162float(h));
    }
}

// ============================================================================
// K1 (tensor core via mma.sync): qkv = w_qkv @ x, bf16 hi/lo split (3 chains).
// grid (6 m-blocks, 256 n-blocks, B), 256 threads (8 warps, 2x4).
// ============================================================================
__global__ __launch_bounds__(256) void k_qkv_mma() {
    extern __shared__ char smem[];
    const int tid = threadIdx.x, wid = tid >> 5, lane = tid & 31;
    const int bz = blockIdx.z;
    const int mBase = blockIdx.x * 128, nBase = blockIdx.y * 128;

    {
        const __nv_bfloat16* xh = g_xt_hi + (size_t)bz * NSP * C;
        const __nv_bfloat16* xl = g_xt_lo + (size_t)bz * NSP * C;
        __nv_bfloat16* sAh = (__nv_bfloat16*)(smem + QS_AHI);
        __nv_bfloat16* sAl = (__nv_bfloat16*)(smem + QS_ALO);
        __nv_bfloat16* sBh = (__nv_bfloat16*)(smem + QS_BHI);
        __nv_bfloat16* sBl = (__nv_bfloat16*)(smem + QS_BLO);
#pragma unroll
        for (int it = 0; it < 8; it++) {
            const int idx = it * 256 + tid;
            const int row = idx >> 4, c8 = (idx & 15) << 3;
            const int so = row * QK_STRIDE + c8;
            const size_t ga = (size_t)(mBase + row) * C + c8;
            const size_t gb = (size_t)(nBase + row) * C + c8;
            *(uint4*)&sAh[so] = *(const uint4*)&g_w_hi[ga];
            *(uint4*)&sAl[so] = *(const uint4*)&g_w_lo[ga];
            *(uint4*)&sBh[so] = *(const uint4*)&xh[gb];
            *(uint4*)&sBl[so] = *(const uint4*)&xl[gb];
        }
    }
    __syncthreads();

    const uint32_t sb = smem_u32(smem);
    const int warpM = (wid >> 2) * 64;
    const int warpN = (wid & 3) * 32;

    const uint32_t aOff =
        (uint32_t)((warpM + (lane & 15)) * QK_STRIDE + ((lane >> 4) << 3)) * 2;
    const int bg = lane >> 3;
    const uint32_t bOff =
        (uint32_t)((warpN + ((bg >> 1) << 3) + (lane & 7)) * QK_STRIDE +
                   ((bg & 1) << 3)) * 2;

    float acc[4][4][4] = {};

#pragma unroll
    for (int ks = 0; ks < 8; ks++) {
        const uint32_t kOff = (uint32_t)ks * 32;
        uint32_t bh[4][2], bl[4][2];
#pragma unroll
        for (int p = 0; p < 2; p++) {
            const uint32_t po = (uint32_t)(p * 16 * QK_STRIDE * 2);
            uint32_t r[4];
            ldsm4(r, sb + QS_BHI + bOff + po + kOff);
            bh[p * 2][0] = r[0]; bh[p * 2][1] = r[1];
            bh[p * 2 + 1][0] = r[2]; bh[p * 2 + 1][1] = r[3];
            ldsm4(r, sb + QS_BLO + bOff + po + kOff);
            bl[p * 2][0] = r[0]; bl[p * 2][1] = r[1];
            bl[p * 2 + 1][0] = r[2]; bl[p * 2 + 1][1] = r[3];
        }
#pragma unroll
        for (int mi = 0; mi < 4; mi++) {
            const uint32_t mo = (uint32_t)(mi * 16 * QK_STRIDE * 2);
            uint32_t ah[4], al[4];
            ldsm4(ah, sb + QS_AHI + aOff + mo + kOff);
            ldsm4(al, sb + QS_ALO + aOff + mo + kOff);
#pragma unroll
            for (int ni = 0; ni < 4; ni++) {
                mma_bf16(acc[mi][ni], ah, bh[ni]);
                mma_bf16(acc[mi][ni], ah, bl[ni]);
                mma_bf16(acc[mi][ni], al, bh[ni]);
            }
        }
    }

    __syncthreads();
    float* stage = (float*)smem;           // [128][132]
#pragma unroll
    for (int mi = 0; mi < 4; mi++) {
        const int r0 = warpM + mi * 16 + (lane >> 2);
#pragma unroll
        for (int ni = 0; ni < 4; ni++) {
            const int c0 = warpN + ni * 8 + (lane & 3) * 2;
            stage[r0 * 132 + c0]           = acc[mi][ni][0];
            stage[r0 * 132 + c0 + 1]       = acc[mi][ni][1];
            stage[(r0 + 8) * 132 + c0]     = acc[mi][ni][2];
            stage[(r0 + 8) * 132 + c0 + 1] = acc[mi][ni][3];
        }
    }
    __syncthreads();
    float* Cp = g_qkv + ((size_t)bz * M3 + mBase) * NSP + nBase;
#pragma unroll
    for (int it = 0; it < 16; it++) {
        const int idx = it * 256 + tid;
        const int row = idx >> 5, c4 = (idx & 31) << 2;
        *(float4*)&Cp[(size_t)row * NSP + c4] = *(float4*)&stage[row * 132 + c4];
    }
}

// ============================================================================
// K2: softmaxed q, transposed, bf16 hi/lo.  p[c][n] = QSCALE*exp(q)/sum_c exp(q)
// One 32x32 block spans exactly one head -> column stats computed in-block.
// grid (NSP/32, HEADS, B), block (32, 8)
// ============================================================================
__global__ __launch_bounds__(256) void k_cvt_q() {
    __shared__ float t[32][33];
    __shared__ float red[8][33];
    __shared__ float qs[32];
    const int b = blockIdx.z, h = blockIdx.y, n0 = blockIdx.x * 32;
    const int tx = threadIdx.x, ty = threadIdx.y;
    const float* qp = g_qkv + ((size_t)b * M3 + h * DH) * NSP;

#pragma unroll
    for (int j = 0; j < 4; j++)
        t[ty + 8 * j][tx] = qp[(size_t)(ty + 8 * j) * NSP + n0 + tx];
    __syncthreads();

    // exp in place + per-column (n = tx) partial sums over c
    float part = 0.f;
#pragma unroll
    for (int j = 0; j < 4; j++) {
        float e = __expf(t[ty + 8 * j][tx]);
        t[ty + 8 * j][tx] = e;
        part += e;
    }
    red[ty][tx] = part;
    __syncthreads();
    if (ty == 0) {
        float s = 0.f;
#pragma unroll
        for (int jj = 0; jj < 8; jj++) s += red[jj][tx];
        qs[tx] = QSCALE / s;
    }
    __syncthreads();

    // transposed write: lane tx -> c, rows n = ty*4..ty*4+3 (coalesced bf16)
    __nv_bfloat16* ph = g_pt_hi + (size_t)b * NSP * HID;
    __nv_bfloat16* pl = g_pt_lo + (size_t)b * NSP * HID;
#pragma unroll
    for (int i = 0; i < 4; i++) {
        const int n = ty * 4 + i;
        float p = t[tx][n] * qs[n];
        __nv_bfloat16 hh = __float2bfloat16(p);
        const size_t o = (size_t)(n0 + n) * HID + h * DH + tx;
        ph[o] = hh;
        pl[o] = __float2bfloat16(p - __bfloat162float(hh));
    }
}

// ============================================================================
// K3: context partials + k-rowsum partials (no max subtraction):
//   ctxp[sp,b,h,d,e] = sum_n exp(k[d,n]) * v[e,n]
//   ksump[sp,b,h,d]  = sum_n exp(k[d,n])
// grid (NSPLIT, HEADS, B), 256 threads
// ============================================================================
__global__ __launch_bounds__(256) void k_ctx() {
    const int sp = blockIdx.x, h = blockIdx.y, b = blockIdx.z;
    const float* kp = g_qkv + ((size_t)b * M3 + HID     + h * DH) * NSP;
    const float* vp = g_qkv + ((size_t)b * M3 + 2 * HID + h * DH) * NSP;

    __shared__ float ks[32][132];
    __shared__ float vs[32][132];

    const int tid = threadIdx.x;
    const int lane = tid & 31, warp = tid >> 5;
    const int d0 = tid >> 4;
    const int e0 = tid & 15;
    float a00 = 0, a01 = 0, a10 = 0, a11 = 0;
    float racc[4] = {0, 0, 0, 0};
    const int nb = sp * 1024;

    for (int t = 0; t < 8; t++) {
        const int n0 = nb + t * 128;
#pragma unroll
        for (int i = 0; i < 4; i++) {
            int v4 = tid + i * 256;
            int row = v4 >> 5, col = (v4 & 31) << 2;
            float4 kv = *(const float4*)&kp[(size_t)row * NSP + n0 + col];
            float e0v = __expf(kv.x), e1v = __expf(kv.y);
            float e2v = __expf(kv.z), e3v = __expf(kv.w);
            ks[row][col + 0] = e0v; ks[row][col + 1] = e1v;
            ks[row][col + 2] = e2v; ks[row][col + 3] = e3v;
            *(float4*)&vs[row][col] = *(const float4*)&vp[(size_t)row * NSP + n0 + col];
            // warp-exclusive row: shuffle-reduce the exp sums
            float ls = e0v + e1v + e2v + e3v;
#pragma unroll
            for (int off = 16; off > 0; off >>= 1)
                ls += __shfl_xor_sync(0xFFFFFFFFu, ls, off);
            if (lane == 0) racc[i] += ls;
        }
        __syncthreads();
#pragma unroll
        for (int j = 0; j < 128; j += 4) {
            float4 ka = *(const float4*)&ks[d0][j];
            float4 kb = *(const float4*)&ks[d0 + 16][j];
            float4 va = *(const float4*)&vs[e0][j];
            float4 vb = *(const float4*)&vs[e0 + 16][j];
            a00 = fmaf(ka.x, va.x, fmaf(ka.y, va.y, fmaf(ka.z, va.z, fmaf(ka.w, va.w, a00))));
            a01 = fmaf(ka.x, vb.x, fmaf(ka.y, vb.y, fmaf(ka.z, vb.z, fmaf(ka.w, vb.w, a01))));
            a10 = fmaf(kb.x, va.x, fmaf(kb.y, va.y, fmaf(kb.z, va.z, fmaf(kb.w, va.w, a10))));
            a11 = fmaf(kb.x, vb.x, fmaf(kb.y, vb.y, fmaf(kb.z, vb.z, fmaf(kb.w, vb.w, a11))));
        }
        __syncthreads();
    }
    float* cp = &g_ctxp[(((size_t)sp * B + b) * HEADS + h) * (DH * DH)];
    cp[d0 * 32 + e0]             = a00;
    cp[d0 * 32 + e0 + 16]        = a01;
    cp[(d0 + 16) * 32 + e0]      = a10;
    cp[(d0 + 16) * 32 + e0 + 16] = a11;
    if (lane == 0) {
#pragma unroll
        for (int i = 0; i < 4; i++)
            g_ksump[((sp * B + b) * HEADS + h) * DH + warp + 8 * i] = racc[i];
    }
}

// ============================================================================
// K4: reduce ctx & ksum partials, normalize, fold with w_out -> bf16 hi/lo:
//     M[b][o][h*32+d] = sum_e w_out[o][h*32+e] * ctx[b,h,d,e] / ksum[b,h,d]
// grid B, 256 threads
// ============================================================================
__global__ __launch_bounds__(256) void k_fold(const float* __restrict__ wout) {
    const int b = blockIdx.x;
    __shared__ float ctx[HEADS * DH * DH];
    __shared__ float ks_s[HID];
    const int tid = threadIdx.x;

    {
        float s = 0.f;
        for (int sp = 0; sp < NSPLIT; sp++)
            s += g_ksump[(sp * B + b) * HID + tid];
        ks_s[tid] = s;
    }
    __syncthreads();

    for (int idx = tid; idx < HEADS * DH * DH; idx += 256) {
        float s = 0.f;
        for (int sp = 0; sp < NSPLIT; sp++)
            s += g_ctxp[(((size_t)sp * B + b) * HEADS) * (DH * DH) + idx];
        const int h = idx >> 10, de = idx & 1023, d = de >> 5;
        ctx[idx] = s / ks_s[h * DH + d];
    }
    __syncthreads();

    for (int idx = tid; idx < C * HID; idx += 256) {
        const int o = idx >> 8, cc = idx & 255;
        const int h = cc >> 5, d = cc & 31;
        const float* wrow = &wout[o * HID + h * DH];
        const float* crow = &ctx[h * (DH * DH) + d * 32];
        float s = 0.f;
#pragma unroll
        for (int e = 0; e < DH; e++) s = fmaf(wrow[e], crow[e], s);
        __nv_bfloat16 hh = __float2bfloat16(s);
        g_M_hi[(size_t)b * C * HID + idx] = hh;
        g_M_lo[(size_t)b * C * HID + idx] =
            __float2bfloat16(s - __bfloat162float(hh));
    }
}

// ============================================================================
// K5 (tensor core): out[b][o][n] = sum_c M[o][c] * p[c][n] + bias[o]
// Same structure as k_qkv_mma; K=256 as two resident halves.
// grid (NSP/128, B), 256 threads
// ============================================================================
__global__ __launch_bounds__(256) void k_out_mma(float* __restrict__ out,
                                                const float* __restrict__ bout) {
    extern __shared__ char smem[];
    const int tid = threadIdx.x, wid = tid >> 5, lane = tid & 31;
    const int bz = blockIdx.y;
    const int nBase = blockIdx.x * 128;

    const uint32_t sb = smem_u32(smem);
    const int warpM = (wid >> 2) * 64;
    const int warpN = (wid & 3) * 32;
    const uint32_t aOff =
        (uint32_t)((warpM + (lane & 15)) * QK_STRIDE + ((lane >> 4) << 3)) * 2;
    const int bg = lane >> 3;
    const uint32_t bOff =
        (uint32_t)((warpN + ((bg >> 1) << 3) + (lane & 7)) * QK_STRIDE +
                   ((bg & 1) << 3)) * 2;

    float acc[4][4][4] = {};

    for (int kh = 0; kh < 2; kh++) {
        if (kh) __syncthreads();   // all warps done reading previous tiles
        {
            const __nv_bfloat16* mh = g_M_hi + (size_t)bz * C * HID + kh * 128;
            const __nv_bfloat16* ml = g_M_lo + (size_t)bz * C * HID + kh * 128;
            const __nv_bfloat16* ph = g_pt_hi + (size_t)bz * NSP * HID + kh * 128;
            const __nv_bfloat16* pl = g_pt_lo + (size_t)bz * NSP * HID + kh * 128;
            __nv_bfloat16* sAh = (__nv_bfloat16*)(smem + QS_AHI);
            __nv_bfloat16* sAl = (__nv_bfloat16*)(smem + QS_ALO);
            __nv_bfloat16* sBh = (__nv_bfloat16*)(smem + QS_BHI);
            __nv_bfloat16* sBl = (__nv_bfloat16*)(smem + QS_BLO);
#pragma unroll
            for (int it = 0; it < 8; it++) {
                const int idx = it * 256 + tid;
                const int row = idx >> 4, c8 = (idx & 15) << 3;
                const int so = row * QK_STRIDE + c8;
                const size_t ga = (size_t)row * HID + c8;
                const size_t gb = (size_t)(nBase + row) * HID + c8;
                *(uint4*)&sAh[so] = *(const uint4*)&mh[ga];
                *(uint4*)&sAl[so] = *(const uint4*)&ml[ga];
                *(uint4*)&sBh[so] = *(const uint4*)&ph[gb];
                *(uint4*)&sBl[so] = *(const uint4*)&pl[gb];
            }
        }
        __syncthreads();

#pragma unroll
        for (int ks = 0; ks < 8; ks++) {
            const uint32_t kOff = (uint32_t)ks * 32;
            uint32_t bh[4][2], bl[4][2];
#pragma unroll
            for (int p = 0; p < 2; p++) {
                const uint32_t po = (uint32_t)(p * 16 * QK_STRIDE * 2);
                uint32_t r[4];
                ldsm4(r, sb + QS_BHI + bOff + po + kOff);
                bh[p * 2][0] = r[0]; bh[p * 2][1] = r[1];
                bh[p * 2 + 1][0] = r[2]; bh[p * 2 + 1][1] = r[3];
                ldsm4(r, sb + QS_BLO + bOff + po + kOff);
                bl[p * 2][0] = r[0]; bl[p * 2][1] = r[1];
                bl[p * 2 + 1][0] = r[2]; bl[p * 2 + 1][1] = r[3];
            }
#pragma unroll
            for (int mi = 0; mi < 4; mi++) {
                const uint32_t mo = (uint32_t)(mi * 16 * QK_STRIDE * 2);
                uint32_t ah[4], al[4];
                ldsm4(ah, sb + QS_AHI + aOff + mo + kOff);
                ldsm4(al, sb + QS_ALO + aOff + mo + kOff);
#pragma unroll
                for (int ni = 0; ni < 4; ni++) {
                    mma_bf16(acc[mi][ni], ah, bh[ni]);
                    mma_bf16(acc[mi][ni], ah, bl[ni]);
                    mma_bf16(acc[mi][ni], al, bh[ni]);
                }
            }
        }
    }

    // epilogue: stage (note: result is out^T tile [o][n] with o as m, n as n)
    __syncthreads();
    float* stage = (float*)smem;           // [128][132]
#pragma unroll
    for (int mi = 0; mi < 4; mi++) {
        const int r0 = warpM + mi * 16 + (lane >> 2);
#pragma unroll
        for (int ni = 0; ni < 4; ni++) {
            const int c0 = warpN + ni * 8 + (lane & 3) * 2;
            stage[r0 * 132 + c0]           = acc[mi][ni][0];
            stage[r0 * 132 + c0 + 1]       = acc[mi][ni][1];
            stage[(r0 + 8) * 132 + c0]     = acc[mi][ni][2];
            stage[(r0 + 8) * 132 + c0 + 1] = acc[mi][ni][3];
        }
    }
    __syncthreads();
    float* Cp = out + (size_t)bz * C * NSP + nBase;
#pragma unroll
    for (int it = 0; it < 16; it++) {
        const int idx = it * 256 + tid;
        const int row = idx >> 5, c4 = (idx & 31) << 2;
        const float bb = __ldg(&bout[row]);
        float4 v = *(float4*)&stage[row * 132 + c4];
        v.x += bb; v.y += bb; v.z += bb; v.w += bb;
        *(float4*)&Cp[(size_t)row * NSP + c4] = v;
    }
}

// ============================================================================
extern "C" void kernel_launch(void* const* d_in, const int* in_sizes, int n_in,
                              void* d_out, int out_size) {
    const float* x    = (const float*)d_in[0];
    const float* wqkv = (const float*)d_in[1];
    const float* wout = (const float*)d_in[2];
    const float* bout = (const float*)d_in[3];
    float* out = (float*)d_out;

    cudaFuncSetAttribute(k_qkv_mma, cudaFuncAttributeMaxDynamicSharedMemorySize,
                         QS_TOTAL);
    cudaFuncSetAttribute(k_out_mma, cudaFuncAttributeMaxDynamicSharedMemorySize,
                         QS_TOTAL);

    k_cvt_w  <<<(M3 * C + 255) / 256, 256>>>(wqkv);
    k_cvt_x  <<<dim3(NSP / 32, C / 32, B), dim3(32, 8)>>>(x);
    k_qkv_mma<<<dim3(M3 / 128, NSP / 128, B), 256, QS_TOTAL>>>();
    k_cvt_q  <<<dim3(NSP / 32, HEADS, B), dim3(32, 8)>>>();
    k_ctx    <<<dim3(NSPLIT, HEADS, B), 256>>>();
    k_fold   <<<B, 256>>>(wout);
    k_out_mma<<<dim3(NSP / 128, B), 256, QS_TOTAL>>>(out, bout);
}